// round 3
// baseline (speedup 1.0000x reference)
#include <cuda_runtime.h>
#include <stdint.h>

// Problem constants (fixed by setup_inputs)
#define B_SZ     32
#define C_SZ     384
#define T_SZ     1024
#define MAXLEN   8192
#define CH_OUT   (C_SZ + 2)          // 386
#define MAX_DUR  10000

#define THREADS     256
#define POS_PER_TH  8
#define POS_CHUNK   (THREADS * POS_PER_TH)   // 2048
#define N_PCHUNK    (MAXLEN / POS_CHUNK)     // 4
#define CH_GRP      8
#define N_YGRP      (C_SZ / CH_GRP + 1)      // 48 full groups + 1 extras group

// Scratch (allocation-free rule: device globals)
__device__ int g_ends[B_SZ][T_SZ];   // inclusive cumsum of clipped durations
__device__ int g_dval[B_SZ][T_SZ];   // clipped durations
__device__ int g_tok [B_SZ][MAXLEN]; // token index per output position, -1 = invalid (monotone tail)

// ---------------------------------------------------------------------------
// Kernel 1: per-batch scan + token-map scatter + tail fill + mel_len.
// One block per batch, 1024 threads. Warp-shfl scan (2 block syncs).
// ---------------------------------------------------------------------------
__global__ __launch_bounds__(1024) void prep_kernel(
    const int* __restrict__ duration,   // [B, T] int32
    float* __restrict__ out, long long out_size)
{
    const int b    = blockIdx.x;
    const int tid  = threadIdx.x;
    const int lane = tid & 31;
    const int wid  = tid >> 5;

    __shared__ int wsum[32];

    // clip(|d|, 1, MAX_DUR)
    int dv = duration[b * T_SZ + tid];
    int ad = dv < 0 ? -dv : dv;
    int d  = ad < 1 ? 1 : (ad > MAX_DUR ? MAX_DUR : ad);

    // warp inclusive scan
    int v = d;
    #pragma unroll
    for (int off = 1; off < 32; off <<= 1) {
        int u = __shfl_up_sync(0xFFFFFFFFu, v, off);
        if (lane >= off) v += u;
    }
    if (lane == 31) wsum[wid] = v;
    __syncthreads();

    // warp 0 scans the 32 warp sums (exclusive)
    if (wid == 0) {
        int w = wsum[lane];
        #pragma unroll
        for (int off = 1; off < 32; off <<= 1) {
            int u = __shfl_up_sync(0xFFFFFFFFu, w, off);
            if (lane >= off) w += u;
        }
        wsum[lane] = w;            // inclusive warp-sum scan
    }
    __syncthreads();

    int warp_off = (wid == 0) ? 0 : wsum[wid - 1];
    int end   = v + warp_off;      // inclusive scan value
    int start = end - d;
    int total = wsum[31];

    g_ends[b][tid] = end;
    g_dval[b][tid] = d;

    // Scatter token index to its output span (spans are disjoint)
    int e = end < MAXLEN ? end : MAXLEN;
    for (int p = start; p < e; ++p)
        g_tok[b][p] = tid;

    // Tail fill: invalid positions -> -1
    for (int p = total + tid; p < MAXLEN; p += blockDim.x)
        g_tok[b][p] = -1;

    // mel_len (second output), appended after out[0]; guarded by out_size
    if (tid == 0) {
        long long base = (long long)B_SZ * CH_OUT * MAXLEN;
        if (base + b < out_size)
            out[base + b] = (float)total;
    }
}

// ---------------------------------------------------------------------------
// Kernel 2: channel-grouped streaming expand-gather.
// grid = (N_PCHUNK=4, N_YGRP=49, B=32), 256 threads.
// Each thread owns 8 consecutive positions; tok loaded ONCE (2x int4),
// reused across 8 channels. Streaming stores (evict-first).
// ---------------------------------------------------------------------------
__global__ __launch_bounds__(THREADS) void expand_kernel(
    const float* __restrict__ x,   // [B, C, T]
    float* __restrict__ out)       // [B, CH_OUT, MAXLEN] (+ mel_len tail)
{
    const int b    = blockIdx.z;
    const int yg   = blockIdx.y;
    const int pos0 = (blockIdx.x * THREADS + threadIdx.x) * POS_PER_TH;

    const int4 ta = *reinterpret_cast<const int4*>(&g_tok[b][pos0]);
    const int4 tb = *reinterpret_cast<const int4*>(&g_tok[b][pos0 + 4]);
    const int t[8] = { ta.x, ta.y, ta.z, ta.w, tb.x, tb.y, tb.z, tb.w };
    const bool all_invalid = (ta.x < 0);   // tok map monotone: -1 tail only

    float* const outb = out + (long long)b * CH_OUT * MAXLEN + pos0;

    if (yg < C_SZ / CH_GRP) {
        const int ch0 = yg * CH_GRP;
        const float* const xb = x + ((long long)b * C_SZ + ch0) * T_SZ;
        #pragma unroll
        for (int c = 0; c < CH_GRP; ++c) {
            float4 v0 = {0.f, 0.f, 0.f, 0.f}, v1 = {0.f, 0.f, 0.f, 0.f};
            if (!all_invalid) {
                const float* __restrict__ xrow = xb + c * T_SZ;
                v0.x = (t[0] >= 0) ? __ldg(&xrow[t[0]]) : 0.f;
                v0.y = (t[1] >= 0) ? __ldg(&xrow[t[1]]) : 0.f;
                v0.z = (t[2] >= 0) ? __ldg(&xrow[t[2]]) : 0.f;
                v0.w = (t[3] >= 0) ? __ldg(&xrow[t[3]]) : 0.f;
                v1.x = (t[4] >= 0) ? __ldg(&xrow[t[4]]) : 0.f;
                v1.y = (t[5] >= 0) ? __ldg(&xrow[t[5]]) : 0.f;
                v1.z = (t[6] >= 0) ? __ldg(&xrow[t[6]]) : 0.f;
                v1.w = (t[7] >= 0) ? __ldg(&xrow[t[7]]) : 0.f;
            }
            float* o = outb + (long long)(ch0 + c) * MAXLEN;
            __stcs(reinterpret_cast<float4*>(o),     v0);
            __stcs(reinterpret_cast<float4*>(o + 4), v1);
        }
    } else {
        // ch 384 = idx_in, ch 385 = length
        float iv[8], lv[8];
        #pragma unroll
        for (int i = 0; i < 8; ++i) { iv[i] = 0.f; lv[i] = 0.f; }
        if (!all_invalid) {
            #pragma unroll
            for (int i = 0; i < 8; ++i) {
                if (t[i] >= 0) {
                    int dd = g_dval[b][t[i]];
                    int st = g_ends[b][t[i]] - dd;
                    iv[i] = (float)(pos0 + i - st);
                    lv[i] = (float)dd;
                }
            }
        }
        float* oi = outb + (long long)C_SZ * MAXLEN;
        float* ol = oi + MAXLEN;
        __stcs(reinterpret_cast<float4*>(oi),     make_float4(iv[0], iv[1], iv[2], iv[3]));
        __stcs(reinterpret_cast<float4*>(oi + 4), make_float4(iv[4], iv[5], iv[6], iv[7]));
        __stcs(reinterpret_cast<float4*>(ol),     make_float4(lv[0], lv[1], lv[2], lv[3]));
        __stcs(reinterpret_cast<float4*>(ol + 4), make_float4(lv[4], lv[5], lv[6], lv[7]));
    }
}

// ---------------------------------------------------------------------------
extern "C" void kernel_launch(void* const* d_in, const int* in_sizes, int n_in,
                              void* d_out, int out_size)
{
    const float* x   = (const float*)d_in[0];
    const int*   dur = (const int*)d_in[1];
    float*       out = (float*)d_out;

    prep_kernel<<<B_SZ, 1024>>>(dur, out, (long long)out_size);

    dim3 grid(N_PCHUNK, N_YGRP, B_SZ);
    expand_kernel<<<grid, THREADS>>>(x, out);
}

// round 6
// speedup vs baseline: 1.3472x; 1.3472x over previous
#include <cuda_runtime.h>
#include <stdint.h>

// Problem constants (fixed by setup_inputs)
#define B_SZ     32
#define C_SZ     384
#define T_SZ     1024
#define MAXLEN   8192
#define CH_OUT   (C_SZ + 2)          // 386
#define MAX_DUR  10000

#define THREADS     256
#define POS_PER_TH  4
#define POS_CHUNK   (THREADS * POS_PER_TH)   // 1024
#define N_PCHUNK    (MAXLEN / POS_CHUNK)     // 8
#define CH_GRP      4
#define N_YGRP      (C_SZ / CH_GRP + 1)      // 96 full groups + 1 extras group

// Scratch (allocation-free rule: device globals)
__device__ int g_ends[B_SZ][T_SZ];   // inclusive cumsum of clipped durations
__device__ int g_dval[B_SZ][T_SZ];   // clipped durations
__device__ int g_tok [B_SZ][MAXLEN]; // token per output position, -1 = invalid (monotone tail)

// ---------------------------------------------------------------------------
// Kernel 1: per-batch scan + token-map scatter + tail fill + mel_len.
// One block per batch, 1024 threads. Warp-shfl scan (2 block syncs).
// ---------------------------------------------------------------------------
__global__ __launch_bounds__(1024) void prep_kernel(
    const int* __restrict__ duration,   // [B, T] int32
    float* __restrict__ out, long long out_size)
{
    const int b    = blockIdx.x;
    const int tid  = threadIdx.x;
    const int lane = tid & 31;
    const int wid  = tid >> 5;

    __shared__ int wsum[32];

    // clip(|d|, 1, MAX_DUR)
    int dv = duration[b * T_SZ + tid];
    int ad = dv < 0 ? -dv : dv;
    int d  = ad < 1 ? 1 : (ad > MAX_DUR ? MAX_DUR : ad);

    // warp inclusive scan
    int v = d;
    #pragma unroll
    for (int off = 1; off < 32; off <<= 1) {
        int u = __shfl_up_sync(0xFFFFFFFFu, v, off);
        if (lane >= off) v += u;
    }
    if (lane == 31) wsum[wid] = v;
    __syncthreads();

    // warp 0 scans the 32 warp sums
    if (wid == 0) {
        int w = wsum[lane];
        #pragma unroll
        for (int off = 1; off < 32; off <<= 1) {
            int u = __shfl_up_sync(0xFFFFFFFFu, w, off);
            if (lane >= off) w += u;
        }
        wsum[lane] = w;            // inclusive warp-sum scan
    }
    __syncthreads();

    int warp_off = (wid == 0) ? 0 : wsum[wid - 1];
    int end   = v + warp_off;      // inclusive scan value
    int start = end - d;
    int total = wsum[31];

    g_ends[b][tid] = end;
    g_dval[b][tid] = d;

    // Scatter token index to its output span (spans are disjoint)
    int e = end < MAXLEN ? end : MAXLEN;
    for (int p = start; p < e; ++p)
        g_tok[b][p] = tid;

    // Tail fill: invalid positions -> -1
    for (int p = total + tid; p < MAXLEN; p += blockDim.x)
        g_tok[b][p] = -1;

    // mel_len (second output), appended after out[0]; guarded by out_size
    if (tid == 0) {
        long long base = (long long)B_SZ * CH_OUT * MAXLEN;
        if (base + b < out_size)
            out[base + b] = (float)total;
    }
}

// ---------------------------------------------------------------------------
// Kernel 2: streaming expand-gather, 4 channels per block.
// grid = (N_PCHUNK=8, N_YGRP=97, B=32), 256 threads, 4 positions/thread.
// tok loaded ONCE per thread (int4), reused across 4 channels.
// ---------------------------------------------------------------------------
__global__ __launch_bounds__(THREADS) void expand_kernel(
    const float* __restrict__ x,   // [B, C, T]
    float* __restrict__ out)       // [B, CH_OUT, MAXLEN] (+ mel_len tail)
{
    const int b    = blockIdx.z;
    const int yg   = blockIdx.y;
    const int pos0 = (blockIdx.x * THREADS + threadIdx.x) * POS_PER_TH;

    const int4 t4 = *reinterpret_cast<const int4*>(&g_tok[b][pos0]);

    float* const outb = out + (long long)b * CH_OUT * MAXLEN + pos0;

    if (yg < C_SZ / CH_GRP) {
        const int ch0 = yg * CH_GRP;
        const float* const xb = x + ((long long)b * C_SZ + ch0) * T_SZ;
        #pragma unroll
        for (int c = 0; c < CH_GRP; ++c) {
            const float* __restrict__ xrow = xb + c * T_SZ;
            float4 v;
            v.x = (t4.x >= 0) ? __ldg(&xrow[t4.x]) : 0.0f;
            v.y = (t4.y >= 0) ? __ldg(&xrow[t4.y]) : 0.0f;
            v.z = (t4.z >= 0) ? __ldg(&xrow[t4.z]) : 0.0f;
            v.w = (t4.w >= 0) ? __ldg(&xrow[t4.w]) : 0.0f;
            *reinterpret_cast<float4*>(outb + (long long)(ch0 + c) * MAXLEN) = v;
        }
    } else {
        // ch 384 = idx_in, ch 385 = length
        float4 iv = {0.f, 0.f, 0.f, 0.f};
        float4 lv = {0.f, 0.f, 0.f, 0.f};
        if (t4.x >= 0) {
            int dd = g_dval[b][t4.x];
            iv.x = (float)(pos0 + 0 - (g_ends[b][t4.x] - dd)); lv.x = (float)dd;
        }
        if (t4.y >= 0) {
            int dd = g_dval[b][t4.y];
            iv.y = (float)(pos0 + 1 - (g_ends[b][t4.y] - dd)); lv.y = (float)dd;
        }
        if (t4.z >= 0) {
            int dd = g_dval[b][t4.z];
            iv.z = (float)(pos0 + 2 - (g_ends[b][t4.z] - dd)); lv.z = (float)dd;
        }
        if (t4.w >= 0) {
            int dd = g_dval[b][t4.w];
            iv.w = (float)(pos0 + 3 - (g_ends[b][t4.w] - dd)); lv.w = (float)dd;
        }
        float* oi = outb + (long long)C_SZ * MAXLEN;
        *reinterpret_cast<float4*>(oi)          = iv;
        *reinterpret_cast<float4*>(oi + MAXLEN) = lv;
    }
}

// ---------------------------------------------------------------------------
extern "C" void kernel_launch(void* const* d_in, const int* in_sizes, int n_in,
                              void* d_out, int out_size)
{
    const float* x   = (const float*)d_in[0];
    const int*   dur = (const int*)d_in[1];
    float*       out = (float*)d_out;

    prep_kernel<<<B_SZ, 1024>>>(dur, out, (long long)out_size);

    dim3 grid(N_PCHUNK, N_YGRP, B_SZ);
    expand_kernel<<<grid, THREADS>>>(x, out);
}